// round 4
// baseline (speedup 1.0000x reference)
#include <cuda_runtime.h>

#define IMG   64
#define OUTW  61
#define NB    256
#define NOUT  (OUTW * OUTW)

// Deterministic scratch + completion ticket (reset by the last block each call,
// so the kernel is graph-replayable).
__device__ float        g_partials[NB];
__device__ unsigned int g_ticket = 0;

__global__ __launch_bounds__(256) void conv_hybrid_fused(
    const float* __restrict__ data,
    const float* __restrict__ conv_w,
    const float* __restrict__ conv_b,
    float* __restrict__ out)
{
    __shared__ float img[IMG * IMG];   // 16 KB
    __shared__ float w[16];
    __shared__ float red[8];
    __shared__ bool  is_last;

    const int b = blockIdx.x;
    const int t = threadIdx.x;

    if (t < 16) w[t] = conv_w[t];

    // Coalesced float4 stage of this image (4096 floats = 1024 float4).
    const float4* src = (const float4*)(data + (size_t)b * IMG * IMG);
    float4*       dst = (float4*)img;
    #pragma unroll
    for (int k = 0; k < 4; k++)
        dst[t + k * 256] = src[t + k * 256];
    __syncthreads();

    const float bias = conv_b[0];

    float lsum = 0.0f;
    #pragma unroll 3
    for (int idx = t; idx < NOUT; idx += 256) {
        const int i = idx / OUTW;
        const int j = idx - i * OUTW;
        float acc = bias;
        #pragma unroll
        for (int di = 0; di < 4; di++) {
            #pragma unroll
            for (int dj = 0; dj < 4; dj++)
                acc = fmaf(img[(i + di) * IMG + (j + dj)], w[di * 4 + dj], acc);
        }
        // sigmoid; __expf accuracy is far inside the 1e-3 tolerance on a mean.
        lsum += 1.0f / (1.0f + __expf(-acc));
    }

    // Deterministic intra-block tree reduce.
    #pragma unroll
    for (int o = 16; o; o >>= 1)
        lsum += __shfl_xor_sync(0xffffffffu, lsum, o);
    if ((t & 31) == 0) red[t >> 5] = lsum;
    __syncthreads();

    if (t == 0) {
        float v = 0.0f;
        #pragma unroll
        for (int k = 0; k < 8; k++) v += red[k];
        g_partials[b] = v;
        __threadfence();                       // publish partial before ticket
        unsigned int tk = atomicAdd(&g_ticket, 1u);
        is_last = (tk == NB - 1);
    }
    __syncthreads();

    if (!is_last) return;

    // ── Last block: global reduce (fixed index order → deterministic) ──
    if (t == 0) atomicExch(&g_ticket, 0u);     // rearm for graph replay

    float v = g_partials[t];                   // 256 partials, 1 per thread
    #pragma unroll
    for (int o = 16; o; o >>= 1)
        v += __shfl_xor_sync(0xffffffffu, v, o);
    if ((t & 31) == 0) red[t >> 5] = v;
    __syncthreads();

    float total = 0.0f;
    #pragma unroll
    for (int k = 0; k < 8; k++) total += red[k];

    // Quantum term: state stays exactly uniform under RX(theta in {0, pi_f32})
    // and the CX chain, so qexp = (c^2+s^2)^k - 1 with theta = float32(pi).
    // c^2+s^2 == 1.0f exactly in fp32 -> qexp == 0 for every batch element,
    // independent of the thresholded data. So out[b] = 0.5 * classical_mean.
    const float mean = total * (1.0f / ((float)NB * (float)NOUT));
    out[t] = 0.5f * mean;
}

extern "C" void kernel_launch(void* const* d_in, const int* in_sizes, int n_in,
                              void* d_out, int out_size)
{
    const float* data   = (const float*)d_in[0];
    const float* conv_w = (const float*)d_in[1];
    const float* conv_b = (const float*)d_in[2];
    float* out = (float*)d_out;

    conv_hybrid_fused<<<NB, 256>>>(data, conv_w, conv_b, out);
}

// round 5
// speedup vs baseline: 1.6738x; 1.6738x over previous
#include <cuda_runtime.h>

#define IMG    64
#define OUTW   61
#define NB     256            // batch
#define SLICES 4
#define NBLK   (NB * SLICES)  // 1024 CTAs
#define NOUT   (OUTW * OUTW)

// Deterministic scratch + completion ticket (rearmed by the last block each
// call, so the kernel is graph-replayable).
__device__ float        g_partials[NBLK];
__device__ unsigned int g_ticket = 0;

__global__ __launch_bounds__(256) void conv_hybrid_fused(
    const float* __restrict__ data,
    const float* __restrict__ conv_w,
    const float* __restrict__ conv_b,
    float* __restrict__ out)
{
    __shared__ float4 sm4[19 * 16];   // up to 19 input rows x 64 floats (4.75 KB)
    __shared__ float  red[8];
    __shared__ bool   is_last;

    const int t = threadIdx.x;
    const int b = blockIdx.x >> 2;          // image
    const int s = blockIdx.x & 3;           // row-slice
    const int nrows_out = (s < 3) ? 16 : 13;
    const int in_rows   = (s < 3) ? 19 : 16;

    // Weights + bias into registers (uniform, L1/const cached).
    float wr[16];
    #pragma unroll
    for (int k = 0; k < 16; k++) wr[k] = __ldg(&conv_w[k]);
    const float bias = __ldg(&conv_b[0]);

    // Stage this slice's input rows (coalesced float4).
    const float4* src = (const float4*)(data + (size_t)b * IMG * IMG + s * 16 * IMG);
    const int count4 = in_rows * 16;        // 304 or 256 float4
    for (int k = t; k < count4; k += 256)
        sm4[k] = src[k];
    __syncthreads();

    // One task per thread: task = r*16 + g  →  outputs (row r, cols 4g..4g+3).
    float lsum = 0.0f;
    const int ntasks = nrows_out * 16;      // 256 or 208
    if (t < ntasks) {
        const int r = t >> 4;
        const int g = t & 15;

        float acc0 = bias, acc1 = bias, acc2 = bias, acc3 = bias;
        #pragma unroll
        for (int dr = 0; dr < 4; dr++) {
            const int row = r + dr;
            const float4 f0 = sm4[row * 16 + g];
            const float4 f1 = (g < 15) ? sm4[row * 16 + g + 1]
                                       : make_float4(0.f, 0.f, 0.f, 0.f);
            const float v0 = f0.x, v1 = f0.y, v2 = f0.z, v3 = f0.w;
            const float v4 = f1.x, v5 = f1.y, v6 = f1.z;
            const float w0 = wr[dr * 4 + 0], w1 = wr[dr * 4 + 1];
            const float w2 = wr[dr * 4 + 2], w3 = wr[dr * 4 + 3];
            acc0 = fmaf(v0, w0, acc0); acc0 = fmaf(v1, w1, acc0);
            acc0 = fmaf(v2, w2, acc0); acc0 = fmaf(v3, w3, acc0);
            acc1 = fmaf(v1, w0, acc1); acc1 = fmaf(v2, w1, acc1);
            acc1 = fmaf(v3, w2, acc1); acc1 = fmaf(v4, w3, acc1);
            acc2 = fmaf(v2, w0, acc2); acc2 = fmaf(v3, w1, acc2);
            acc2 = fmaf(v4, w2, acc2); acc2 = fmaf(v5, w3, acc2);
            acc3 = fmaf(v3, w0, acc3); acc3 = fmaf(v4, w1, acc3);
            acc3 = fmaf(v5, w2, acc3); acc3 = fmaf(v6, w3, acc3);
        }

        // sigmoid; __expf accuracy is far inside the 1e-3 tolerance on a mean.
        const int j = g * 4;
        if (j + 0 < OUTW) lsum += 1.0f / (1.0f + __expf(-acc0));
        if (j + 1 < OUTW) lsum += 1.0f / (1.0f + __expf(-acc1));
        if (j + 2 < OUTW) lsum += 1.0f / (1.0f + __expf(-acc2));
        if (j + 3 < OUTW) lsum += 1.0f / (1.0f + __expf(-acc3));
    }

    // Deterministic intra-block tree reduce.
    #pragma unroll
    for (int o = 16; o; o >>= 1)
        lsum += __shfl_xor_sync(0xffffffffu, lsum, o);
    if ((t & 31) == 0) red[t >> 5] = lsum;
    __syncthreads();

    if (t == 0) {
        float v = 0.0f;
        #pragma unroll
        for (int k = 0; k < 8; k++) v += red[k];
        g_partials[blockIdx.x] = v;
        __threadfence();                       // publish partial before ticket
        is_last = (atomicAdd(&g_ticket, 1u) == NBLK - 1);
    }
    __syncthreads();

    if (!is_last) return;

    // ── Last block: global reduce over 1024 partials (fixed order). ──
    if (t == 0) atomicExch(&g_ticket, 0u);     // rearm for graph replay

    float v = 0.0f;
    #pragma unroll
    for (int k = 0; k < 4; k++)                // fixed order → deterministic
        v += g_partials[t + k * 256];
    #pragma unroll
    for (int o = 16; o; o >>= 1)
        v += __shfl_xor_sync(0xffffffffu, v, o);
    if ((t & 31) == 0) red[t >> 5] = v;
    __syncthreads();

    float total = 0.0f;
    #pragma unroll
    for (int k = 0; k < 8; k++) total += red[k];

    // Quantum term: the state stays exactly uniform under RX(theta in
    // {0, float32(pi)}) and the CX chain, so qexp = (c^2+s^2)^k - 1 and
    // c^2+s^2 == 1.0f exactly in fp32  →  qexp == 0 for every batch element.
    // Hence out[b] = 0.5 * classical_mean for all b.
    const float mean = total * (1.0f / ((float)NB * (float)NOUT));
    out[t] = 0.5f * mean;
}

extern "C" void kernel_launch(void* const* d_in, const int* in_sizes, int n_in,
                              void* d_out, int out_size)
{
    const float* data   = (const float*)d_in[0];
    const float* conv_w = (const float*)d_in[1];
    const float* conv_b = (const float*)d_in[2];
    float* out = (float*)d_out;

    conv_hybrid_fused<<<NBLK, 256>>>(data, conv_w, conv_b, out);
}